// round 7
// baseline (speedup 1.0000x reference)
#include <cuda_runtime.h>
#include <cuda_bf16.h>

// actions: [B=4096, T=256, A=64] fp32
// out[b,0,a] = x[b,0,a]
// out[b,t,a] = out[b,t-1,a] + clip(x[b,t,a] - x[b,t-1,a], -0.5, 0.5)
//
// Decoupled segmented scan, v2: CTA per batch row, 512 threads.
// Thread = (chunk c in 0..31, float4 lane a4 in 0..15); chunk = 8 timesteps.
// Halved chunk vs R6 -> regs ~56 (was 128) -> 32 warps/SM (occ ~47%), finer
// phase interleave across warps/CTAs; same 131 KB/SM in-flight load bytes.

#define TT     256
#define ROW4   16            // float4 lanes per (b,t) row
#define CHUNK  8             // timesteps per thread
#define NCHUNK (TT / CHUNK)  // 32
#define MAXD   0.5f

__device__ __forceinline__ float4 clip4(const float4 a, const float4 b)
{
    float4 d;
    d.x = fminf(fmaxf(a.x - b.x, -MAXD), MAXD);
    d.y = fminf(fmaxf(a.y - b.y, -MAXD), MAXD);
    d.z = fminf(fmaxf(a.z - b.z, -MAXD), MAXD);
    d.w = fminf(fmaxf(a.w - b.w, -MAXD), MAXD);
    return d;
}

__device__ __forceinline__ float4 add4(const float4 a, const float4 b)
{
    return make_float4(a.x + b.x, a.y + b.y, a.z + b.z, a.w + b.w);
}

__global__ __launch_bounds__(512, 2) void smooth_scan_kernel(
    const float4* __restrict__ in, float4* __restrict__ out)
{
    __shared__ float4 s_last[NCHUNK][ROW4];  // raw x at each chunk's last t
    __shared__ float4 s_pref[NCHUNK][ROW4];  // chunk sums -> exclusive prefixes

    const unsigned b   = blockIdx.x;
    const unsigned tid = threadIdx.x;
    const unsigned a4  = tid & 15;   // float4 lane within row
    const unsigned c   = tid >> 4;   // time chunk (0..31)

    const size_t base = (size_t)b * (TT * ROW4) + (size_t)c * (CHUNK * ROW4) + a4;

    // ---- Phase 1: dependency-free streaming load ----
    float4 x[CHUNK];
    #pragma unroll
    for (int i = 0; i < CHUNK; ++i)
        x[i] = in[base + (size_t)i * ROW4];

    s_last[c][a4] = x[CHUNK - 1];
    __syncthreads();

    // ---- Phase 2a: in-place local scan ----
    // chunk 0: v[0] = x[0] (carries the base term); chunk c>0: v[0] = clipped
    // diff vs previous chunk's last raw x. v[i] = v[i-1] + clip(x[i]-x[i-1]).
    {
        float4 raw_prev = x[0];
        if (c != 0) {
            float4 xp = s_last[c - 1][a4];
            x[0] = clip4(raw_prev, xp);
        }
        #pragma unroll
        for (int i = 1; i < CHUNK; ++i) {
            float4 cur = x[i];
            x[i] = add4(x[i - 1], clip4(cur, raw_prev));
            raw_prev = cur;
        }
    }

    // ---- Phase 2b: exclusive scan of chunk sums across the 32 chunks ----
    s_pref[c][a4] = x[CHUNK - 1];
    __syncthreads();

    if (tid < ROW4) {                 // one thread per lane scans 32 chunks
        float4 run = make_float4(0.f, 0.f, 0.f, 0.f);
        #pragma unroll
        for (int cc = 0; cc < NCHUNK; ++cc) {
            float4 s = s_pref[cc][tid];
            s_pref[cc][tid] = run;
            run = add4(run, s);
        }
    }
    __syncthreads();

    const float4 P = s_pref[c][a4];

    // ---- Phase 3: streaming store ----
    #pragma unroll
    for (int i = 0; i < CHUNK; ++i)
        out[base + (size_t)i * ROW4] = add4(x[i], P);
}

extern "C" void kernel_launch(void* const* d_in, const int* in_sizes, int n_in,
                              void* d_out, int out_size)
{
    const float4* in  = (const float4*)d_in[0];
    float4*       out = (float4*)d_out;

    smooth_scan_kernel<<<4096, NCHUNK * ROW4>>>(in, out);  // 4096 x 512
}